// round 9
// baseline (speedup 1.0000x reference)
#include <cuda_runtime.h>
#include <cuda_bf16.h>
#include <mma.h>
#include <cstdint>

using namespace nvcuda;

#define NP 8
#define HD 1024
#define BD 2048
#define BM 128
#define BN 64
#define BK 32
#define APITCH 40        // 32+8 elems
#define BPITCH 72        // 64+8 elems

// ---------------- device scratch ----------------
__device__ float g_v[NP];    // (1-alpha)*u[j]
__device__ float g_cw[NP];   // alpha*u[j]

__device__ __nv_bfloat16 g_Wi_hi[HD * HD];   // A1: W_input [m,k]
__device__ __nv_bfloat16 g_Wi_lo[HD * HD];
__device__ __nv_bfloat16 g_We_hi[HD * HD];   // B1: W_eff   [k,n]
__device__ __nv_bfloat16 g_We_lo[HD * HD];
__device__ __nv_bfloat16 g_M_hi[HD * HD];    // B2: M       [k,n]
__device__ __nv_bfloat16 g_M_lo[HD * HD];
__device__ __nv_bfloat16 g_x_hi[BD * HD];    // A2: x       [b,k]
__device__ __nv_bfloat16 g_x_lo[BD * HD];
__device__ float g_P[2 * HD * HD];           // gemm1 split-K partials
__device__ float g_cr[BD * HD];              // coherent reduction

// ---------------- kernel 1: scalars ----------------
__global__ void prep_kernel(const float* __restrict__ J, const float* __restrict__ t_ptr) {
    if (threadIdx.x != 0) return;
    const float t = t_ptr[0];
    float alpha = expf(-t / 51.0f);
    alpha = fminf(fmaxf(alpha, 0.0f), 1.0f);
    const float phase = 2.0f * 3.14159265358979323846f * 20.0f * t / 1000.0f;
    float colsum[NP];
#pragma unroll
    for (int j = 0; j < NP; j++) colsum[j] = 0.0f;
    for (int i = 0; i < NP; i++) {
        float row[NP];
        float mx = -1e30f;
#pragma unroll
        for (int j = 0; j < NP; j++) {
            float js = 0.5f * (J[i * NP + j] + J[j * NP + i]);
            row[j] = cosf(phase * js);
            mx = fmaxf(mx, row[j]);
        }
        float s = 0.0f;
#pragma unroll
        for (int j = 0; j < NP; j++) { row[j] = expf(row[j] - mx); s += row[j]; }
        float inv_s = 1.0f / s;
#pragma unroll
        for (int j = 0; j < NP; j++) colsum[j] += row[j] * inv_s;
    }
    const float scale = alpha / (float)(NP * NP);
#pragma unroll
    for (int j = 0; j < NP; j++) {
        float u = scale * colsum[j];
        g_v[j]  = (1.0f - alpha) * u;
        g_cw[j] = alpha * u;
    }
}

// ---------------- kernel 2: W_eff build + split, and W_input split ----------------
__global__ void build_weff_kernel(const float* __restrict__ Wp, const float* __restrict__ Wi) {
    const int e = (blockIdx.x * blockDim.x + threadIdx.x) * 4;
    float4 s = make_float4(0.f, 0.f, 0.f, 0.f);
#pragma unroll
    for (int j = 0; j < NP; j++) {
        const float4 w = *(const float4*)&Wp[(size_t)j * (HD * HD) + e];
        const float v = g_v[j];
        s.x = fmaf(v, w.x, s.x); s.y = fmaf(v, w.y, s.y);
        s.z = fmaf(v, w.z, s.z); s.w = fmaf(v, w.w, s.w);
    }
    __nv_bfloat16 hi[4], lo[4];
    float sv[4] = {s.x, s.y, s.z, s.w};
#pragma unroll
    for (int i = 0; i < 4; i++) {
        hi[i] = __float2bfloat16(sv[i]);
        lo[i] = __float2bfloat16(sv[i] - __bfloat162float(hi[i]));
    }
    *(uint2*)&g_We_hi[e] = *(uint2*)hi;
    *(uint2*)&g_We_lo[e] = *(uint2*)lo;

    const float4 w = *(const float4*)&Wi[e];
    float wv[4] = {w.x, w.y, w.z, w.w};
#pragma unroll
    for (int i = 0; i < 4; i++) {
        hi[i] = __float2bfloat16(wv[i]);
        lo[i] = __float2bfloat16(wv[i] - __bfloat162float(hi[i]));
    }
    *(uint2*)&g_Wi_hi[e] = *(uint2*)hi;
    *(uint2*)&g_Wi_lo[e] = *(uint2*)lo;
}

// ---------------- kernel 3: split x ----------------
__global__ void split_x_kernel(const float* __restrict__ x) {
    const int e = (blockIdx.x * blockDim.x + threadIdx.x) * 4;
    const float4 v4 = *(const float4*)&x[e];
    float v[4] = {v4.x, v4.y, v4.z, v4.w};
    __nv_bfloat16 hi[4], lo[4];
#pragma unroll
    for (int i = 0; i < 4; i++) {
        hi[i] = __float2bfloat16(v[i]);
        lo[i] = __float2bfloat16(v[i] - __bfloat162float(hi[i]));
    }
    *(uint2*)&g_x_hi[e] = *(uint2*)hi;
    *(uint2*)&g_x_lo[e] = *(uint2*)lo;
}

// ---------------- kernel 4: coherent reduction (pure BW) ----------------
__global__ void coh_reduce_kernel(const float* __restrict__ coh) {
    const int idx = blockIdx.x * blockDim.x + threadIdx.x;
    const int e = idx * 4;
    const int b = e >> 10;
    const int h = e & 1023;
    float4 acc = make_float4(0.f, 0.f, 0.f, 0.f);
#pragma unroll
    for (int j = 0; j < NP; j++) {
        const float4 c = *(const float4*)&coh[((size_t)b * NP + j) * HD + h];
        const float w = g_cw[j];
        acc.x = fmaf(w, c.x, acc.x);
        acc.y = fmaf(w, c.y, acc.y);
        acc.z = fmaf(w, c.z, acc.z);
        acc.w = fmaf(w, c.w, acc.w);
    }
    *(float4*)&g_cr[e] = acc;
}

// ---------------- kernel 6: combine split-K partials -> M hi/lo ----------------
__global__ void fix_m_kernel() {
    const int e = (blockIdx.x * blockDim.x + threadIdx.x) * 4;
    const float4 p0 = *(const float4*)&g_P[e];
    const float4 p1 = *(const float4*)&g_P[HD * HD + e];
    float v[4] = {p0.x + p1.x, p0.y + p1.y, p0.z + p1.z, p0.w + p1.w};
    __nv_bfloat16 hi[4], lo[4];
#pragma unroll
    for (int i = 0; i < 4; i++) {
        hi[i] = __float2bfloat16(v[i]);
        lo[i] = __float2bfloat16(v[i] - __bfloat162float(hi[i]));
    }
    *(uint2*)&g_M_hi[e] = *(uint2*)hi;
    *(uint2*)&g_M_lo[e] = *(uint2*)lo;
}

// ---------------- cp.async helper ----------------
__device__ __forceinline__ void cp16(void* s, const void* g) {
    unsigned sa = (unsigned)__cvta_generic_to_shared(s);
    asm volatile("cp.async.cg.shared.global [%0], [%1], 16;\n" :: "r"(sa), "l"(g));
}
#define CP_COMMIT() asm volatile("cp.async.commit_group;\n")
#define CP_WAIT1()  asm volatile("cp.async.wait_group 1;\n")
#define CP_WAIT0()  asm volatile("cp.async.wait_group 0;\n")

// ---------------- 3-stage pipelined bf16x3 HMMA GEMM ----------------
// 256 threads = 8 warps (4m x 2n), warp tile 32x32 (2x2 wmma), tile 128x64.
// MODE 0: f32 partial store (split-K). MODE 1: out = acc + g_cr.
template<int MODE>
__device__ __forceinline__ void gemm_body(
    const __nv_bfloat16* __restrict__ Ah, const __nv_bfloat16* __restrict__ Al,
    const __nv_bfloat16* __restrict__ Bh, const __nv_bfloat16* __restrict__ Bl,
    float* __restrict__ Cout, int kOff, int nt)
{
    constexpr int A_ONE  = BM * APITCH * 2;
    constexpr int B_ONE  = BK * BPITCH * 2;
    constexpr int OFF_AL = A_ONE;
    constexpr int OFF_BH = 2 * A_ONE;
    constexpr int OFF_BL = 2 * A_ONE + B_ONE;
    constexpr int STAGE  = 2 * A_ONE + 2 * B_ONE;   // 29696 B

    extern __shared__ __align__(16) unsigned char smem[];

    const int tid    = threadIdx.x;
    const int wid    = tid >> 5;
    const int lane   = tid & 31;
    const int warp_m = wid & 3;
    const int warp_n = wid >> 2;
    const int mBase  = blockIdx.y * BM;
    const int nBase  = blockIdx.x * BN;

    auto load_stage = [&](int s, int kt) {
        const int k0 = kOff + kt * BK;
        unsigned char* st = smem + s * STAGE;
        // A: 128 rows x 32 cols -> 512 16B chunks each
#pragma unroll
        for (int i = 0; i < 2; i++) {
            const int c   = tid + i * 256;
            const int row = c >> 2;
            const int ch  = c & 3;
            const int off = row * (APITCH * 2) + ch * 16;
            const size_t go = (size_t)(mBase + row) * HD + k0 + ch * 8;
            cp16(st + off,          Ah + go);
            cp16(st + OFF_AL + off, Al + go);
        }
        // B: 32 rows x 64 cols -> 256 16B chunks each
        {
            const int row = tid >> 3;
            const int ch  = tid & 7;
            const int off = row * (BPITCH * 2) + ch * 16;
            const size_t go = (size_t)(k0 + row) * HD + nBase + ch * 8;
            cp16(st + OFF_BH + off, Bh + go);
            cp16(st + OFF_BL + off, Bl + go);
        }
        CP_COMMIT();
    };

    wmma::fragment<wmma::accumulator, 16, 16, 16, float> acc[2][2];
#pragma unroll
    for (int mi = 0; mi < 2; mi++)
#pragma unroll
        for (int ni = 0; ni < 2; ni++) wmma::fill_fragment(acc[mi][ni], 0.0f);

    load_stage(0, 0);
    load_stage(1, 1);

    for (int it = 0; it < nt; ++it) {
        if (it + 1 < nt) CP_WAIT1(); else CP_WAIT0();
        __syncthreads();
        if (it + 2 < nt) load_stage((it + 2) % 3, it + 2);

        const unsigned char* st = smem + (it % 3) * STAGE;
        const __nv_bfloat16* pAh = (const __nv_bfloat16*)(st);
        const __nv_bfloat16* pAl = (const __nv_bfloat16*)(st + OFF_AL);
        const __nv_bfloat16* pBh = (const __nv_bfloat16*)(st + OFF_BH);
        const __nv_bfloat16* pBl = (const __nv_bfloat16*)(st + OFF_BL);

#pragma unroll
        for (int kc = 0; kc < 2; kc++) {
            wmma::fragment<wmma::matrix_a, 16, 16, 16, __nv_bfloat16, wmma::row_major> fa_h[2], fa_l[2];
            wmma::fragment<wmma::matrix_b, 16, 16, 16, __nv_bfloat16, wmma::row_major> fb_h[2], fb_l[2];
#pragma unroll
            for (int mi = 0; mi < 2; mi++) {
                const int row = warp_m * 32 + mi * 16;
                wmma::load_matrix_sync(fa_h[mi], pAh + row * APITCH + kc * 16, APITCH);
                wmma::load_matrix_sync(fa_l[mi], pAl + row * APITCH + kc * 16, APITCH);
            }
#pragma unroll
            for (int ni = 0; ni < 2; ni++) {
                const int col = warp_n * 32 + ni * 16;
                wmma::load_matrix_sync(fb_h[ni], pBh + (kc * 16) * BPITCH + col, BPITCH);
                wmma::load_matrix_sync(fb_l[ni], pBl + (kc * 16) * BPITCH + col, BPITCH);
            }
            // pass-major: dependent acc reuse 4 MMAs apart
#pragma unroll
            for (int mi = 0; mi < 2; mi++)
#pragma unroll
                for (int ni = 0; ni < 2; ni++)
                    wmma::mma_sync(acc[mi][ni], fa_h[mi], fb_h[ni], acc[mi][ni]);
#pragma unroll
            for (int mi = 0; mi < 2; mi++)
#pragma unroll
                for (int ni = 0; ni < 2; ni++)
                    wmma::mma_sync(acc[mi][ni], fa_h[mi], fb_l[ni], acc[mi][ni]);
#pragma unroll
            for (int mi = 0; mi < 2; mi++)
#pragma unroll
                for (int ni = 0; ni < 2; ni++)
                    wmma::mma_sync(acc[mi][ni], fa_l[mi], fb_h[ni], acc[mi][ni]);
        }
    }

    if (MODE == 0) {
        // direct f32 partial store
#pragma unroll
        for (int mi = 0; mi < 2; mi++)
#pragma unroll
            for (int ni = 0; ni < 2; ni++) {
                float* cp = Cout + (size_t)(mBase + warp_m * 32 + mi * 16) * HD
                          + nBase + warp_n * 32 + ni * 16;
                wmma::store_matrix_sync(cp, acc[mi][ni], HD, wmma::mem_row_major);
            }
    } else {
        __syncthreads();
        float* buf = (float*)smem + wid * 512;
#pragma unroll
        for (int mi = 0; mi < 2; mi++) {
#pragma unroll
            for (int ni = 0; ni < 2; ni++)
                wmma::store_matrix_sync(buf + ni * 16, acc[mi][ni], 32, wmma::mem_row_major);
            __syncwarp();
#pragma unroll
            for (int p = 0; p < 4; p++) {
                const int idx = p * 128 + lane * 4;
                const int r   = idx >> 5;
                const int c   = idx & 31;
                float4 v = *(float4*)&buf[r * 32 + c];
                const int b   = mBase + warp_m * 32 + mi * 16 + r;
                const int col = nBase + warp_n * 32 + c;
                const float4 cr = *(const float4*)&g_cr[(size_t)b * HD + col];
                v.x += cr.x; v.y += cr.y; v.z += cr.z; v.w += cr.w;
                *(float4*)&Cout[(size_t)b * HD + col] = v;
            }
            __syncwarp();
        }
    }
}

// ---------------- entry points (globals bound in device code) ----------------
__global__ void __launch_bounds__(256) gemm1_kernel() {
    gemm_body<0>(g_Wi_hi, g_Wi_lo, g_We_hi, g_We_lo,
                 g_P + (size_t)blockIdx.z * HD * HD, blockIdx.z * (HD / 2), 16);
}
__global__ void __launch_bounds__(256) gemm2_kernel(float* __restrict__ Cf) {
    gemm_body<1>(g_x_hi, g_x_lo, g_M_hi, g_M_lo, Cf, 0, 32);
}

#define SMB (3 * (2 * (BM * APITCH * 2) + 2 * (BK * BPITCH * 2)))   // 89088

// ---------------- launch ----------------
extern "C" void kernel_launch(void* const* d_in, const int* in_sizes, int n_in,
                              void* d_out, int out_size) {
    (void)in_sizes; (void)n_in; (void)out_size;
    const float* x   = (const float*)d_in[0];
    const float* Wi  = (const float*)d_in[1];
    const float* Wp  = (const float*)d_in[2];
    const float* J   = (const float*)d_in[3];
    const float* coh = (const float*)d_in[4];
    const float* t   = (const float*)d_in[5];
    float* out = (float*)d_out;

    cudaFuncSetAttribute(gemm1_kernel, cudaFuncAttributeMaxDynamicSharedMemorySize, SMB);
    cudaFuncSetAttribute(gemm2_kernel, cudaFuncAttributeMaxDynamicSharedMemorySize, SMB);

    prep_kernel<<<1, 32>>>(J, t);
    build_weff_kernel<<<(HD * HD / 4) / 256, 256>>>(Wp, Wi);
    split_x_kernel<<<(BD * HD / 4) / 256, 256>>>(x);
    coh_reduce_kernel<<<(BD * HD / 4) / 256, 256>>>(coh);

    {   // GEMM1 split-K=2: grid 16 x 8 x 2 = 256 CTAs (2/SM co-resident)
        dim3 g(HD / BN, HD / BM, 2);
        gemm1_kernel<<<g, 256, SMB>>>();
    }
    fix_m_kernel<<<(HD * HD / 4) / 256, 256>>>();
    {   // GEMM2: grid 16 x 16 = 256 CTAs (2/SM co-resident)
        dim3 g(HD / BN, BD / BM);
        gemm2_kernel<<<g, 256, SMB>>>(out);
    }
}

// round 10
// speedup vs baseline: 1.3708x; 1.3708x over previous
#include <cuda_runtime.h>
#include <cuda_bf16.h>
#include <mma.h>
#include <cstdint>

using namespace nvcuda;

#define NP 8
#define HD 1024
#define BD 2048
#define BM 128
#define BN 64
#define BK 32
#define APITCH 40        // 32+8 elems (gemm1 A pitch)
#define BPITCH 72        // 64+8 elems

// gemm2 (single-pass) geometry
#define BK2 64
#define NT2 16           // 1024/64
#define AP2 72           // 64+8 elems

// ---------------- device scratch ----------------
__device__ float g_v[NP];    // (1-alpha)*u[j]
__device__ float g_cw[NP];   // alpha*u[j]

__device__ __nv_bfloat16 g_Wi_hi[HD * HD];   // A1: W_input [m,k]
__device__ __nv_bfloat16 g_Wi_lo[HD * HD];
__device__ __nv_bfloat16 g_We_hi[HD * HD];   // B1: W_eff   [k,n]
__device__ __nv_bfloat16 g_We_lo[HD * HD];
__device__ __nv_bfloat16 g_M_hi[HD * HD];    // B2: M       [k,n]  (bf16 only)
__device__ __nv_bfloat16 g_x_hi[BD * HD];    // A2: x       [b,k]  (bf16 only)
__device__ float g_P[2 * HD * HD];           // gemm1 split-K partials
__device__ float g_cr[BD * HD];              // coherent reduction

// ---------------- kernel 1: scalars ----------------
__global__ void prep_kernel(const float* __restrict__ J, const float* __restrict__ t_ptr) {
    if (threadIdx.x != 0) return;
    const float t = t_ptr[0];
    float alpha = expf(-t / 51.0f);
    alpha = fminf(fmaxf(alpha, 0.0f), 1.0f);
    const float phase = 2.0f * 3.14159265358979323846f * 20.0f * t / 1000.0f;
    float colsum[NP];
#pragma unroll
    for (int j = 0; j < NP; j++) colsum[j] = 0.0f;
    for (int i = 0; i < NP; i++) {
        float row[NP];
        float mx = -1e30f;
#pragma unroll
        for (int j = 0; j < NP; j++) {
            float js = 0.5f * (J[i * NP + j] + J[j * NP + i]);
            row[j] = cosf(phase * js);
            mx = fmaxf(mx, row[j]);
        }
        float s = 0.0f;
#pragma unroll
        for (int j = 0; j < NP; j++) { row[j] = expf(row[j] - mx); s += row[j]; }
        float inv_s = 1.0f / s;
#pragma unroll
        for (int j = 0; j < NP; j++) colsum[j] += row[j] * inv_s;
    }
    const float scale = alpha / (float)(NP * NP);
#pragma unroll
    for (int j = 0; j < NP; j++) {
        float u = scale * colsum[j];
        g_v[j]  = (1.0f - alpha) * u;
        g_cw[j] = alpha * u;
    }
}

// ---------------- kernel 2: W_eff build + split, and W_input split ----------------
__global__ void build_weff_kernel(const float* __restrict__ Wp, const float* __restrict__ Wi) {
    const int e = (blockIdx.x * blockDim.x + threadIdx.x) * 4;
    float4 s = make_float4(0.f, 0.f, 0.f, 0.f);
#pragma unroll
    for (int j = 0; j < NP; j++) {
        const float4 w = *(const float4*)&Wp[(size_t)j * (HD * HD) + e];
        const float v = g_v[j];
        s.x = fmaf(v, w.x, s.x); s.y = fmaf(v, w.y, s.y);
        s.z = fmaf(v, w.z, s.z); s.w = fmaf(v, w.w, s.w);
    }
    __nv_bfloat16 hi[4], lo[4];
    float sv[4] = {s.x, s.y, s.z, s.w};
#pragma unroll
    for (int i = 0; i < 4; i++) {
        hi[i] = __float2bfloat16(sv[i]);
        lo[i] = __float2bfloat16(sv[i] - __bfloat162float(hi[i]));
    }
    *(uint2*)&g_We_hi[e] = *(uint2*)hi;
    *(uint2*)&g_We_lo[e] = *(uint2*)lo;

    const float4 w = *(const float4*)&Wi[e];
    float wv[4] = {w.x, w.y, w.z, w.w};
#pragma unroll
    for (int i = 0; i < 4; i++) {
        hi[i] = __float2bfloat16(wv[i]);
        lo[i] = __float2bfloat16(wv[i] - __bfloat162float(hi[i]));
    }
    *(uint2*)&g_Wi_hi[e] = *(uint2*)hi;
    *(uint2*)&g_Wi_lo[e] = *(uint2*)lo;
}

// ---------------- kernel 3: split x (bf16 only, single-pass gemm2) ----------------
__global__ void split_x_kernel(const float* __restrict__ x) {
    const int e = (blockIdx.x * blockDim.x + threadIdx.x) * 4;
    const float4 v4 = *(const float4*)&x[e];
    __nv_bfloat16 hi[4];
    hi[0] = __float2bfloat16(v4.x);
    hi[1] = __float2bfloat16(v4.y);
    hi[2] = __float2bfloat16(v4.z);
    hi[3] = __float2bfloat16(v4.w);
    *(uint2*)&g_x_hi[e] = *(uint2*)hi;
}

// ---------------- kernel 4: coherent reduction (pure BW) ----------------
__global__ void coh_reduce_kernel(const float* __restrict__ coh) {
    const int idx = blockIdx.x * blockDim.x + threadIdx.x;
    const int e = idx * 4;
    const int b = e >> 10;
    const int h = e & 1023;
    float4 acc = make_float4(0.f, 0.f, 0.f, 0.f);
#pragma unroll
    for (int j = 0; j < NP; j++) {
        const float4 c = *(const float4*)&coh[((size_t)b * NP + j) * HD + h];
        const float w = g_cw[j];
        acc.x = fmaf(w, c.x, acc.x);
        acc.y = fmaf(w, c.y, acc.y);
        acc.z = fmaf(w, c.z, acc.z);
        acc.w = fmaf(w, c.w, acc.w);
    }
    *(float4*)&g_cr[e] = acc;
}

// ---------------- kernel 6: combine split-K partials -> M bf16 ----------------
__global__ void fix_m_kernel() {
    const int e = (blockIdx.x * blockDim.x + threadIdx.x) * 4;
    const float4 p0 = *(const float4*)&g_P[e];
    const float4 p1 = *(const float4*)&g_P[HD * HD + e];
    __nv_bfloat16 hi[4];
    hi[0] = __float2bfloat16(p0.x + p1.x);
    hi[1] = __float2bfloat16(p0.y + p1.y);
    hi[2] = __float2bfloat16(p0.z + p1.z);
    hi[3] = __float2bfloat16(p0.w + p1.w);
    *(uint2*)&g_M_hi[e] = *(uint2*)hi;
}

// ---------------- cp.async helper ----------------
__device__ __forceinline__ void cp16(void* s, const void* g) {
    unsigned sa = (unsigned)__cvta_generic_to_shared(s);
    asm volatile("cp.async.cg.shared.global [%0], [%1], 16;\n" :: "r"(sa), "l"(g));
}
#define CP_COMMIT() asm volatile("cp.async.commit_group;\n")
#define CP_WAIT1()  asm volatile("cp.async.wait_group 1;\n")
#define CP_WAIT0()  asm volatile("cp.async.wait_group 0;\n")

// ---------------- GEMM1: 3-stage pipelined bf16x3 HMMA, split-K ----------------
// 256 threads = 8 warps (4m x 2n), warp tile 32x32, tile 128x64, f32 partial out.
__global__ void __launch_bounds__(256) gemm1_kernel() {
    constexpr int A_ONE  = BM * APITCH * 2;
    constexpr int B_ONE  = BK * BPITCH * 2;
    constexpr int OFF_AL = A_ONE;
    constexpr int OFF_BH = 2 * A_ONE;
    constexpr int OFF_BL = 2 * A_ONE + B_ONE;
    constexpr int STAGE  = 2 * A_ONE + 2 * B_ONE;

    extern __shared__ __align__(16) unsigned char smem[];

    const __nv_bfloat16* __restrict__ Ah = g_Wi_hi;
    const __nv_bfloat16* __restrict__ Al = g_Wi_lo;
    const __nv_bfloat16* __restrict__ Bh = g_We_hi;
    const __nv_bfloat16* __restrict__ Bl = g_We_lo;
    float* __restrict__ Cout = g_P + (size_t)blockIdx.z * HD * HD;
    const int kOff = blockIdx.z * (HD / 2);

    const int tid    = threadIdx.x;
    const int wid    = tid >> 5;
    const int warp_m = wid & 3;
    const int warp_n = wid >> 2;
    const int mBase  = blockIdx.y * BM;
    const int nBase  = blockIdx.x * BN;

    auto load_stage = [&](int s, int kt) {
        const int k0 = kOff + kt * BK;
        unsigned char* st = smem + s * STAGE;
#pragma unroll
        for (int i = 0; i < 2; i++) {
            const int c   = tid + i * 256;
            const int row = c >> 2;
            const int ch  = c & 3;
            const int off = row * (APITCH * 2) + ch * 16;
            const size_t go = (size_t)(mBase + row) * HD + k0 + ch * 8;
            cp16(st + off,          Ah + go);
            cp16(st + OFF_AL + off, Al + go);
        }
        {
            const int row = tid >> 3;
            const int ch  = tid & 7;
            const int off = row * (BPITCH * 2) + ch * 16;
            const size_t go = (size_t)(k0 + row) * HD + nBase + ch * 8;
            cp16(st + OFF_BH + off, Bh + go);
            cp16(st + OFF_BL + off, Bl + go);
        }
        CP_COMMIT();
    };

    wmma::fragment<wmma::accumulator, 16, 16, 16, float> acc[2][2];
#pragma unroll
    for (int mi = 0; mi < 2; mi++)
#pragma unroll
        for (int ni = 0; ni < 2; ni++) wmma::fill_fragment(acc[mi][ni], 0.0f);

    load_stage(0, 0);
    load_stage(1, 1);

    const int nt = 16;
    for (int it = 0; it < nt; ++it) {
        if (it + 1 < nt) CP_WAIT1(); else CP_WAIT0();
        __syncthreads();
        if (it + 2 < nt) load_stage((it + 2) % 3, it + 2);

        const unsigned char* st = smem + (it % 3) * STAGE;
        const __nv_bfloat16* pAh = (const __nv_bfloat16*)(st);
        const __nv_bfloat16* pAl = (const __nv_bfloat16*)(st + OFF_AL);
        const __nv_bfloat16* pBh = (const __nv_bfloat16*)(st + OFF_BH);
        const __nv_bfloat16* pBl = (const __nv_bfloat16*)(st + OFF_BL);

#pragma unroll
        for (int kc = 0; kc < 2; kc++) {
            wmma::fragment<wmma::matrix_a, 16, 16, 16, __nv_bfloat16, wmma::row_major> fa_h[2], fa_l[2];
            wmma::fragment<wmma::matrix_b, 16, 16, 16, __nv_bfloat16, wmma::row_major> fb_h[2], fb_l[2];
#pragma unroll
            for (int mi = 0; mi < 2; mi++) {
                const int row = warp_m * 32 + mi * 16;
                wmma::load_matrix_sync(fa_h[mi], pAh + row * APITCH + kc * 16, APITCH);
                wmma::load_matrix_sync(fa_l[mi], pAl + row * APITCH + kc * 16, APITCH);
            }
#pragma unroll
            for (int ni = 0; ni < 2; ni++) {
                const int col = warp_n * 32 + ni * 16;
                wmma::load_matrix_sync(fb_h[ni], pBh + (kc * 16) * BPITCH + col, BPITCH);
                wmma::load_matrix_sync(fb_l[ni], pBl + (kc * 16) * BPITCH + col, BPITCH);
            }
#pragma unroll
            for (int mi = 0; mi < 2; mi++)
#pragma unroll
                for (int ni = 0; ni < 2; ni++)
                    wmma::mma_sync(acc[mi][ni], fa_h[mi], fb_h[ni], acc[mi][ni]);
#pragma unroll
            for (int mi = 0; mi < 2; mi++)
#pragma unroll
                for (int ni = 0; ni < 2; ni++)
                    wmma::mma_sync(acc[mi][ni], fa_h[mi], fb_l[ni], acc[mi][ni]);
#pragma unroll
            for (int mi = 0; mi < 2; mi++)
#pragma unroll
                for (int ni = 0; ni < 2; ni++)
                    wmma::mma_sync(acc[mi][ni], fa_l[mi], fb_h[ni], acc[mi][ni]);
        }
    }

#pragma unroll
    for (int mi = 0; mi < 2; mi++)
#pragma unroll
        for (int ni = 0; ni < 2; ni++) {
            float* cp = Cout + (size_t)(mBase + warp_m * 32 + mi * 16) * HD
                      + nBase + warp_n * 32 + ni * 16;
            wmma::store_matrix_sync(cp, acc[mi][ni], HD, wmma::mem_row_major);
        }
}

// ---------------- GEMM2: single-pass bf16, BK=64, 3-stage pipeline ----------------
// 256 threads = 8 warps (4m x 2n), warp tile 32x32, tile 128x64.
// out = x @ M + g_cr.
__global__ void __launch_bounds__(256) gemm2_kernel(float* __restrict__ Cf) {
    constexpr int A_ONE  = BM * AP2 * 2;       // 18432
    constexpr int B_ONE  = BK2 * BPITCH * 2;   // 9216
    constexpr int OFF_B  = A_ONE;
    constexpr int STAGE  = A_ONE + B_ONE;      // 27648

    extern __shared__ __align__(16) unsigned char smem[];

    const int tid    = threadIdx.x;
    const int wid    = tid >> 5;
    const int lane   = tid & 31;
    const int warp_m = wid & 3;
    const int warp_n = wid >> 2;
    const int mBase  = blockIdx.y * BM;
    const int nBase  = blockIdx.x * BN;

    auto load_stage = [&](int s, int kt) {
        const int k0 = kt * BK2;
        unsigned char* st = smem + s * STAGE;
        // A: 128 rows x 64 cols = 1024 x 16B chunks -> 4/thread
#pragma unroll
        for (int i = 0; i < 4; i++) {
            const int c   = tid + i * 256;
            const int row = c >> 3;
            const int ch  = c & 7;
            cp16(st + row * (AP2 * 2) + ch * 16,
                 g_x_hi + (size_t)(mBase + row) * HD + k0 + ch * 8);
        }
        // B: 64 rows x 64 cols = 512 x 16B chunks -> 2/thread
#pragma unroll
        for (int i = 0; i < 2; i++) {
            const int c   = tid + i * 256;
            const int row = c >> 3;
            const int ch  = c & 7;
            cp16(st + OFF_B + row * (BPITCH * 2) + ch * 16,
                 g_M_hi + (size_t)(k0 + row) * HD + nBase + ch * 8);
        }
        CP_COMMIT();
    };

    wmma::fragment<wmma::accumulator, 16, 16, 16, float> acc[2][2];
#pragma unroll
    for (int mi = 0; mi < 2; mi++)
#pragma unroll
        for (int ni = 0; ni < 2; ni++) wmma::fill_fragment(acc[mi][ni], 0.0f);

    load_stage(0, 0);
    load_stage(1, 1);

    for (int it = 0; it < NT2; ++it) {
        if (it + 1 < NT2) CP_WAIT1(); else CP_WAIT0();
        __syncthreads();
        if (it + 2 < NT2) load_stage((it + 2) % 3, it + 2);

        const unsigned char* st = smem + (it % 3) * STAGE;
        const __nv_bfloat16* pA = (const __nv_bfloat16*)(st);
        const __nv_bfloat16* pB = (const __nv_bfloat16*)(st + OFF_B);

#pragma unroll
        for (int kc = 0; kc < 4; kc++) {
            wmma::fragment<wmma::matrix_a, 16, 16, 16, __nv_bfloat16, wmma::row_major> fa[2];
            wmma::fragment<wmma::matrix_b, 16, 16, 16, __nv_bfloat16, wmma::row_major> fb[2];
#pragma unroll
            for (int mi = 0; mi < 2; mi++)
                wmma::load_matrix_sync(fa[mi], pA + (warp_m * 32 + mi * 16) * AP2 + kc * 16, AP2);
#pragma unroll
            for (int ni = 0; ni < 2; ni++)
                wmma::load_matrix_sync(fb[ni], pB + (kc * 16) * BPITCH + warp_n * 32 + ni * 16, BPITCH);
#pragma unroll
            for (int mi = 0; mi < 2; mi++)
#pragma unroll
                for (int ni = 0; ni < 2; ni++)
                    wmma::mma_sync(acc[mi][ni], fa[mi], fb[ni], acc[mi][ni]);
        }
    }

    // epilogue: stage via smem, add g_cr, vector store
    __syncthreads();
    float* buf = (float*)smem + wid * 512;
#pragma unroll
    for (int mi = 0; mi < 2; mi++) {
#pragma unroll
        for (int ni = 0; ni < 2; ni++)
            wmma::store_matrix_sync(buf + ni * 16, acc[mi][ni], 32, wmma::mem_row_major);
        __syncwarp();
#pragma unroll
        for (int p = 0; p < 4; p++) {
            const int idx = p * 128 + lane * 4;
            const int r   = idx >> 5;
            const int c   = idx & 31;
            float4 v = *(float4*)&buf[r * 32 + c];
            const int b   = mBase + warp_m * 32 + mi * 16 + r;
            const int col = nBase + warp_n * 32 + c;
            const float4 cr = *(const float4*)&g_cr[(size_t)b * HD + col];
            v.x += cr.x; v.y += cr.y; v.z += cr.z; v.w += cr.w;
            *(float4*)&Cf[(size_t)b * HD + col] = v;
        }
        __syncwarp();
    }
}

#define SMB1 (3 * (2 * (BM * APITCH * 2) + 2 * (BK * BPITCH * 2)))   // 89088
#define SMB2 (3 * (BM * AP2 * 2 + BK2 * BPITCH * 2))                 // 82944

// ---------------- launch ----------------
extern "C" void kernel_launch(void* const* d_in, const int* in_sizes, int n_in,
                              void* d_out, int out_size) {
    (void)in_sizes; (void)n_in; (void)out_size;
    const float* x   = (const float*)d_in[0];
    const float* Wi  = (const float*)d_in[1];
    const float* Wp  = (const float*)d_in[2];
    const float* J   = (const float*)d_in[3];
    const float* coh = (const float*)d_in[4];
    const float* t   = (const float*)d_in[5];
    float* out = (float*)d_out;

    cudaFuncSetAttribute(gemm1_kernel, cudaFuncAttributeMaxDynamicSharedMemorySize, SMB1);
    cudaFuncSetAttribute(gemm2_kernel, cudaFuncAttributeMaxDynamicSharedMemorySize, SMB2);

    prep_kernel<<<1, 32>>>(J, t);
    build_weff_kernel<<<(HD * HD / 4) / 256, 256>>>(Wp, Wi);
    split_x_kernel<<<(BD * HD / 4) / 256, 256>>>(x);
    coh_reduce_kernel<<<(BD * HD / 4) / 256, 256>>>(coh);

    {   // GEMM1 split-K=2: grid 16 x 8 x 2 = 256 CTAs
        dim3 g(HD / BN, HD / BM, 2);
        gemm1_kernel<<<g, 256, SMB1>>>();
    }
    fix_m_kernel<<<(HD * HD / 4) / 256, 256>>>();
    {   // GEMM2 single-pass: grid 16 x 16 = 256 CTAs
        dim3 g(HD / BN, BD / BM);
        gemm2_kernel<<<g, 256, SMB2>>>(out);
    }
}

// round 11
// speedup vs baseline: 1.5074x; 1.0996x over previous
#include <cuda_runtime.h>
#include <cuda_bf16.h>
#include <mma.h>
#include <cstdint>

using namespace nvcuda;

#define NP 8
#define HD 1024
#define BD 2048
#define BM 128
#define BN 128
#define APITCH 40        // gemm1 A pitch: 32+8 elems
#define BPITCH 136       // B pitch: 128+8 elems
#define AP2 72           // gemm2 A pitch: 64+8 elems
#define BK1 32
#define BK2 64
#define NT1 16           // 512/32 per split-K half
#define NT2 16           // 1024/64

// ---------------- device scratch ----------------
__device__ float g_v[NP];    // (1-alpha)*u[j]
__device__ float g_cw[NP];   // alpha*u[j]

__device__ __nv_bfloat16 g_Wi_hi[HD * HD];   // A1 hi
__device__ __nv_bfloat16 g_Wi_lo[HD * HD];   // A1 lo
__device__ __nv_bfloat16 g_We_hi[HD * HD];   // B1 hi (2-pass: no lo needed)
__device__ __nv_bfloat16 g_M_hi[HD * HD];    // B2
__device__ __nv_bfloat16 g_x_hi[BD * HD];    // A2
__device__ float g_P[2 * HD * HD];           // gemm1 split-K partials
__device__ float g_cr[BD * HD];              // coherent reduction

// ---------------- kernel 1: scalars ----------------
__global__ void prep_kernel(const float* __restrict__ J, const float* __restrict__ t_ptr) {
    if (threadIdx.x != 0) return;
    const float t = t_ptr[0];
    float alpha = expf(-t / 51.0f);
    alpha = fminf(fmaxf(alpha, 0.0f), 1.0f);
    const float phase = 2.0f * 3.14159265358979323846f * 20.0f * t / 1000.0f;
    float colsum[NP];
#pragma unroll
    for (int j = 0; j < NP; j++) colsum[j] = 0.0f;
    for (int i = 0; i < NP; i++) {
        float row[NP];
        float mx = -1e30f;
#pragma unroll
        for (int j = 0; j < NP; j++) {
            float js = 0.5f * (J[i * NP + j] + J[j * NP + i]);
            row[j] = cosf(phase * js);
            mx = fmaxf(mx, row[j]);
        }
        float s = 0.0f;
#pragma unroll
        for (int j = 0; j < NP; j++) { row[j] = expf(row[j] - mx); s += row[j]; }
        float inv_s = 1.0f / s;
#pragma unroll
        for (int j = 0; j < NP; j++) colsum[j] += row[j] * inv_s;
    }
    const float scale = alpha / (float)(NP * NP);
#pragma unroll
    for (int j = 0; j < NP; j++) {
        float u = scale * colsum[j];
        g_v[j]  = (1.0f - alpha) * u;
        g_cw[j] = alpha * u;
    }
}

// ---------------- kernel 2: W_eff build (hi only) + W_input split (hi/lo) ----------------
__global__ void build_weff_kernel(const float* __restrict__ Wp, const float* __restrict__ Wi) {
    const int e = (blockIdx.x * blockDim.x + threadIdx.x) * 4;
    float4 s = make_float4(0.f, 0.f, 0.f, 0.f);
#pragma unroll
    for (int j = 0; j < NP; j++) {
        const float4 w = *(const float4*)&Wp[(size_t)j * (HD * HD) + e];
        const float v = g_v[j];
        s.x = fmaf(v, w.x, s.x); s.y = fmaf(v, w.y, s.y);
        s.z = fmaf(v, w.z, s.z); s.w = fmaf(v, w.w, s.w);
    }
    __nv_bfloat16 hi[4], lo[4];
    hi[0] = __float2bfloat16(s.x); hi[1] = __float2bfloat16(s.y);
    hi[2] = __float2bfloat16(s.z); hi[3] = __float2bfloat16(s.w);
    *(uint2*)&g_We_hi[e] = *(uint2*)hi;

    const float4 w = *(const float4*)&Wi[e];
    float wv[4] = {w.x, w.y, w.z, w.w};
#pragma unroll
    for (int i = 0; i < 4; i++) {
        hi[i] = __float2bfloat16(wv[i]);
        lo[i] = __float2bfloat16(wv[i] - __bfloat162float(hi[i]));
    }
    *(uint2*)&g_Wi_hi[e] = *(uint2*)hi;
    *(uint2*)&g_Wi_lo[e] = *(uint2*)lo;
}

// ---------------- kernel 3: x -> bf16 ----------------
__global__ void split_x_kernel(const float* __restrict__ x) {
    const int e = (blockIdx.x * blockDim.x + threadIdx.x) * 4;
    const float4 v4 = *(const float4*)&x[e];
    __nv_bfloat16 hi[4];
    hi[0] = __float2bfloat16(v4.x);
    hi[1] = __float2bfloat16(v4.y);
    hi[2] = __float2bfloat16(v4.z);
    hi[3] = __float2bfloat16(v4.w);
    *(uint2*)&g_x_hi[e] = *(uint2*)hi;
}

// ---------------- kernel 4: coherent reduction (pure BW) ----------------
__global__ void coh_reduce_kernel(const float* __restrict__ coh) {
    const int idx = blockIdx.x * blockDim.x + threadIdx.x;
    const int e = idx * 4;
    const int b = e >> 10;
    const int h = e & 1023;
    float4 acc = make_float4(0.f, 0.f, 0.f, 0.f);
#pragma unroll
    for (int j = 0; j < NP; j++) {
        const float4 c = *(const float4*)&coh[((size_t)b * NP + j) * HD + h];
        const float w = g_cw[j];
        acc.x = fmaf(w, c.x, acc.x);
        acc.y = fmaf(w, c.y, acc.y);
        acc.z = fmaf(w, c.z, acc.z);
        acc.w = fmaf(w, c.w, acc.w);
    }
    *(float4*)&g_cr[e] = acc;
}

// ---------------- kernel 5: combine split-K partials -> M bf16 ----------------
__global__ void fix_m_kernel() {
    const int e = (blockIdx.x * blockDim.x + threadIdx.x) * 4;
    const float4 p0 = *(const float4*)&g_P[e];
    const float4 p1 = *(const float4*)&g_P[HD * HD + e];
    __nv_bfloat16 hi[4];
    hi[0] = __float2bfloat16(p0.x + p1.x);
    hi[1] = __float2bfloat16(p0.y + p1.y);
    hi[2] = __float2bfloat16(p0.z + p1.z);
    hi[3] = __float2bfloat16(p0.w + p1.w);
    *(uint2*)&g_M_hi[e] = *(uint2*)hi;
}

// ---------------- cp.async helper ----------------
__device__ __forceinline__ void cp16(void* s, const void* g) {
    unsigned sa = (unsigned)__cvta_generic_to_shared(s);
    asm volatile("cp.async.cg.shared.global [%0], [%1], 16;\n" :: "r"(sa), "l"(g));
}
#define CP_COMMIT() asm volatile("cp.async.commit_group;\n")
#define CP_WAIT1()  asm volatile("cp.async.wait_group 1;\n")
#define CP_WAIT0()  asm volatile("cp.async.wait_group 0;\n")

// ---------------- GEMM1: 2-pass bf16 ((Ah+Al)@Bh), tile 128x128, split-K=2 ----------------
// 256 thr = 8 warps (4m x 2n); warp tile 32x64 = 2x4 wmma tiles. f32 partial out.
__global__ void __launch_bounds__(256) gemm1_kernel() {
    constexpr int A_ONE  = BM * APITCH * 2;        // 10240
    constexpr int B_ONE  = BK1 * BPITCH * 2;       // 8704
    constexpr int OFF_AL = A_ONE;
    constexpr int OFF_B  = 2 * A_ONE;
    constexpr int STAGE  = 2 * A_ONE + B_ONE;      // 29184

    extern __shared__ __align__(16) unsigned char smem[];

    float* __restrict__ Cout = g_P + (size_t)blockIdx.z * HD * HD;
    const int kOff = blockIdx.z * (HD / 2);

    const int tid    = threadIdx.x;
    const int wid    = tid >> 5;
    const int warp_m = wid & 3;        // 32-row strip
    const int warp_n = wid >> 2;       // 64-col strip
    const int mBase  = blockIdx.y * BM;
    const int nBase  = blockIdx.x * BN;

    auto load_stage = [&](int s, int kt) {
        const int k0 = kOff + kt * BK1;
        unsigned char* st = smem + s * STAGE;
        // A hi+lo: 128 rows x 32 cols = 512 x 16B each
#pragma unroll
        for (int i = 0; i < 2; i++) {
            const int c   = tid + i * 256;
            const int row = c >> 2;
            const int ch  = c & 3;
            const int off = row * (APITCH * 2) + ch * 16;
            const size_t go = (size_t)(mBase + row) * HD + k0 + ch * 8;
            cp16(st + off,          g_Wi_hi + go);
            cp16(st + OFF_AL + off, g_Wi_lo + go);
        }
        // B hi: 32 rows x 128 cols = 512 x 16B
#pragma unroll
        for (int i = 0; i < 2; i++) {
            const int c   = tid + i * 256;
            const int row = c >> 4;
            const int ch  = c & 15;
            cp16(st + OFF_B + row * (BPITCH * 2) + ch * 16,
                 g_We_hi + (size_t)(k0 + row) * HD + nBase + ch * 8);
        }
        CP_COMMIT();
    };

    wmma::fragment<wmma::accumulator, 16, 16, 16, float> acc[2][4];
#pragma unroll
    for (int mi = 0; mi < 2; mi++)
#pragma unroll
        for (int ni = 0; ni < 4; ni++) wmma::fill_fragment(acc[mi][ni], 0.0f);

    load_stage(0, 0);
    load_stage(1, 1);

    for (int it = 0; it < NT1; ++it) {
        if (it + 1 < NT1) CP_WAIT1(); else CP_WAIT0();
        __syncthreads();
        if (it + 2 < NT1) load_stage((it + 2) % 3, it + 2);

        const unsigned char* st = smem + (it % 3) * STAGE;
        const __nv_bfloat16* pAh = (const __nv_bfloat16*)(st);
        const __nv_bfloat16* pAl = (const __nv_bfloat16*)(st + OFF_AL);
        const __nv_bfloat16* pB  = (const __nv_bfloat16*)(st + OFF_B);

#pragma unroll
        for (int kc = 0; kc < 2; kc++) {
            wmma::fragment<wmma::matrix_a, 16, 16, 16, __nv_bfloat16, wmma::row_major> fa_h[2], fa_l[2];
            wmma::fragment<wmma::matrix_b, 16, 16, 16, __nv_bfloat16, wmma::row_major> fb[4];
#pragma unroll
            for (int mi = 0; mi < 2; mi++) {
                const int row = warp_m * 32 + mi * 16;
                wmma::load_matrix_sync(fa_h[mi], pAh + row * APITCH + kc * 16, APITCH);
                wmma::load_matrix_sync(fa_l[mi], pAl + row * APITCH + kc * 16, APITCH);
            }
#pragma unroll
            for (int ni = 0; ni < 4; ni++)
                wmma::load_matrix_sync(fb[ni], pB + (kc * 16) * BPITCH + warp_n * 64 + ni * 16, BPITCH);
            // pass-major: hh then lh (8 independent accs per pass)
#pragma unroll
            for (int mi = 0; mi < 2; mi++)
#pragma unroll
                for (int ni = 0; ni < 4; ni++)
                    wmma::mma_sync(acc[mi][ni], fa_h[mi], fb[ni], acc[mi][ni]);
#pragma unroll
            for (int mi = 0; mi < 2; mi++)
#pragma unroll
                for (int ni = 0; ni < 4; ni++)
                    wmma::mma_sync(acc[mi][ni], fa_l[mi], fb[ni], acc[mi][ni]);
        }
    }

#pragma unroll
    for (int mi = 0; mi < 2; mi++)
#pragma unroll
        for (int ni = 0; ni < 4; ni++) {
            float* cp = Cout + (size_t)(mBase + warp_m * 32 + mi * 16) * HD
                      + nBase + warp_n * 64 + ni * 16;
            wmma::store_matrix_sync(cp, acc[mi][ni], HD, wmma::mem_row_major);
        }
}

// ---------------- GEMM2: single-pass bf16, tile 128x128, BK=64 ----------------
// 256 thr = 8 warps (4m x 2n); warp tile 32x64 = 2x4 wmma. out = x@M + g_cr.
__global__ void __launch_bounds__(256) gemm2_kernel(float* __restrict__ Cf) {
    constexpr int A_ONE = BM * AP2 * 2;        // 18432
    constexpr int B_ONE = BK2 * BPITCH * 2;    // 17408
    constexpr int OFF_B = A_ONE;
    constexpr int STAGE = A_ONE + B_ONE;       // 35840

    extern __shared__ __align__(16) unsigned char smem[];

    const int tid    = threadIdx.x;
    const int wid    = tid >> 5;
    const int lane   = tid & 31;
    const int warp_m = wid & 3;
    const int warp_n = wid >> 2;
    const int mBase  = blockIdx.y * BM;
    const int nBase  = blockIdx.x * BN;

    auto load_stage = [&](int s, int kt) {
        const int k0 = kt * BK2;
        unsigned char* st = smem + s * STAGE;
        // A: 128 rows x 64 cols = 1024 x 16B -> 4/thread
#pragma unroll
        for (int i = 0; i < 4; i++) {
            const int c   = tid + i * 256;
            const int row = c >> 3;
            const int ch  = c & 7;
            cp16(st + row * (AP2 * 2) + ch * 16,
                 g_x_hi + (size_t)(mBase + row) * HD + k0 + ch * 8);
        }
        // B: 64 rows x 128 cols = 1024 x 16B -> 4/thread
#pragma unroll
        for (int i = 0; i < 4; i++) {
            const int c   = tid + i * 256;
            const int row = c >> 4;
            const int ch  = c & 15;
            cp16(st + OFF_B + row * (BPITCH * 2) + ch * 16,
                 g_M_hi + (size_t)(k0 + row) * HD + nBase + ch * 8);
        }
        CP_COMMIT();
    };

    wmma::fragment<wmma::accumulator, 16, 16, 16, float> acc[2][4];
#pragma unroll
    for (int mi = 0; mi < 2; mi++)
#pragma unroll
        for (int ni = 0; ni < 4; ni++) wmma::fill_fragment(acc[mi][ni], 0.0f);

    load_stage(0, 0);
    load_stage(1, 1);

    for (int it = 0; it < NT2; ++it) {
        if (it + 1 < NT2) CP_WAIT1(); else CP_WAIT0();
        __syncthreads();
        if (it + 2 < NT2) load_stage((it + 2) % 3, it + 2);

        const unsigned char* st = smem + (it % 3) * STAGE;
        const __nv_bfloat16* pA = (const __nv_bfloat16*)(st);
        const __nv_bfloat16* pB = (const __nv_bfloat16*)(st + OFF_B);

#pragma unroll
        for (int kc = 0; kc < 4; kc++) {
            wmma::fragment<wmma::matrix_a, 16, 16, 16, __nv_bfloat16, wmma::row_major> fa[2];
            wmma::fragment<wmma::matrix_b, 16, 16, 16, __nv_bfloat16, wmma::row_major> fb[4];
#pragma unroll
            for (int mi = 0; mi < 2; mi++)
                wmma::load_matrix_sync(fa[mi], pA + (warp_m * 32 + mi * 16) * AP2 + kc * 16, AP2);
#pragma unroll
            for (int ni = 0; ni < 4; ni++)
                wmma::load_matrix_sync(fb[ni], pB + (kc * 16) * BPITCH + warp_n * 64 + ni * 16, BPITCH);
#pragma unroll
            for (int mi = 0; mi < 2; mi++)
#pragma unroll
                for (int ni = 0; ni < 4; ni++)
                    wmma::mma_sync(acc[mi][ni], fa[mi], fb[ni], acc[mi][ni]);
        }
    }

    // epilogue: stage 16x64 per warp via smem, add g_cr, float4 store
    __syncthreads();
    float* buf = (float*)smem + wid * 1024;
#pragma unroll
    for (int mi = 0; mi < 2; mi++) {
#pragma unroll
        for (int ni = 0; ni < 4; ni++)
            wmma::store_matrix_sync(buf + ni * 16, acc[mi][ni], 64, wmma::mem_row_major);
        __syncwarp();
#pragma unroll
        for (int p = 0; p < 8; p++) {
            const int idx = p * 128 + lane * 4;
            const int r   = idx >> 6;
            const int c   = idx & 63;
            float4 v = *(float4*)&buf[r * 64 + c];
            const int b   = mBase + warp_m * 32 + mi * 16 + r;
            const int col = nBase + warp_n * 64 + c;
            const float4 cr = *(const float4*)&g_cr[(size_t)b * HD + col];
            v.x += cr.x; v.y += cr.y; v.z += cr.z; v.w += cr.w;
            *(float4*)&Cf[(size_t)b * HD + col] = v;
        }
        __syncwarp();
    }
}

#define SMB1 (3 * (2 * (BM * APITCH * 2) + BK1 * BPITCH * 2))   // 87552
#define SMB2 (3 * (BM * AP2 * 2 + BK2 * BPITCH * 2))            // 107520

// ---------------- launch ----------------
extern "C" void kernel_launch(void* const* d_in, const int* in_sizes, int n_in,
                              void* d_out, int out_size) {
    (void)in_sizes; (void)n_in; (void)out_size;
    const float* x   = (const float*)d_in[0];
    const float* Wi  = (const float*)d_in[1];
    const float* Wp  = (const float*)d_in[2];
    const float* J   = (const float*)d_in[3];
    const float* coh = (const float*)d_in[4];
    const float* t   = (const float*)d_in[5];
    float* out = (float*)d_out;

    cudaFuncSetAttribute(gemm1_kernel, cudaFuncAttributeMaxDynamicSharedMemorySize, SMB1);
    cudaFuncSetAttribute(gemm2_kernel, cudaFuncAttributeMaxDynamicSharedMemorySize, SMB2);

    prep_kernel<<<1, 32>>>(J, t);
    build_weff_kernel<<<(HD * HD / 4) / 256, 256>>>(Wp, Wi);
    split_x_kernel<<<(BD * HD / 4) / 256, 256>>>(x);
    coh_reduce_kernel<<<(BD * HD / 4) / 256, 256>>>(coh);

    {   // GEMM1 2-pass split-K=2: grid 8 x 8 x 2 = 128 CTAs
        dim3 g(HD / BN, HD / BM, 2);
        gemm1_kernel<<<g, 256, SMB1>>>();
    }
    fix_m_kernel<<<(HD * HD / 4) / 256, 256>>>();
    {   // GEMM2 single-pass: grid 8 x 16 = 128 CTAs
        dim3 g(HD / BN, BD / BM);
        gemm2_kernel<<<g, 256, SMB2>>>(out);
    }
}

// round 13
// speedup vs baseline: 1.6304x; 1.0816x over previous
#include <cuda_runtime.h>
#include <cuda_bf16.h>
#include <mma.h>
#include <cstdint>

using namespace nvcuda;

#define NP 8
#define HD 1024
#define BD 2048
#define BM 128
#define BN 128
#define APITCH 40        // gemm1 A pitch: 32+8 elems
#define BPITCH 136       // B pitch: 128+8 elems
#define AP2 72           // gemm2 A pitch: 64+8 elems
#define BK1 32
#define BK2 64
#define NT1 16           // 512/32 per split-K half
#define NT2 16           // 1024/64

// ---------------- device scratch ----------------
__device__ float g_v[NP];    // (1-alpha)*u[j]
__device__ float g_cw[NP];   // alpha*u[j]

__device__ __nv_bfloat16 g_Wi_hi[HD * HD];   // A1 (bf16, single-pass)
__device__ __nv_bfloat16 g_We_hi[HD * HD];   // B1 (bf16)
__device__ __nv_bfloat16 g_M_hi[HD * HD];    // B2
__device__ __nv_bfloat16 g_x_hi[BD * HD];    // A2
__device__ float g_P[2 * HD * HD];           // gemm1 split-K partials
__device__ float g_cr[BD * HD];              // coherent reduction

// ---------------- kernel 1: scalars ----------------
__global__ void prep_kernel(const float* __restrict__ J, const float* __restrict__ t_ptr) {
    if (threadIdx.x != 0) return;
    const float t = t_ptr[0];
    float alpha = expf(-t / 51.0f);
    alpha = fminf(fmaxf(alpha, 0.0f), 1.0f);
    const float phase = 2.0f * 3.14159265358979323846f * 20.0f * t / 1000.0f;
    float colsum[NP];
#pragma unroll
    for (int j = 0; j < NP; j++) colsum[j] = 0.0f;
    for (int i = 0; i < NP; i++) {
        float row[NP];
        float mx = -1e30f;
#pragma unroll
        for (int j = 0; j < NP; j++) {
            float js = 0.5f * (J[i * NP + j] + J[j * NP + i]);
            row[j] = cosf(phase * js);
            mx = fmaxf(mx, row[j]);
        }
        float s = 0.0f;
#pragma unroll
        for (int j = 0; j < NP; j++) { row[j] = expf(row[j] - mx); s += row[j]; }
        float inv_s = 1.0f / s;
#pragma unroll
        for (int j = 0; j < NP; j++) colsum[j] += row[j] * inv_s;
    }
    const float scale = alpha / (float)(NP * NP);
#pragma unroll
    for (int j = 0; j < NP; j++) {
        float u = scale * colsum[j];
        g_v[j]  = (1.0f - alpha) * u;
        g_cw[j] = alpha * u;
    }
}

// ---------------- kernel 2: W_eff build + W_input -> bf16 ----------------
__global__ void build_weff_kernel(const float* __restrict__ Wp, const float* __restrict__ Wi) {
    const int e = (blockIdx.x * blockDim.x + threadIdx.x) * 4;
    float4 s = make_float4(0.f, 0.f, 0.f, 0.f);
#pragma unroll
    for (int j = 0; j < NP; j++) {
        const float4 w = *(const float4*)&Wp[(size_t)j * (HD * HD) + e];
        const float v = g_v[j];
        s.x = fmaf(v, w.x, s.x); s.y = fmaf(v, w.y, s.y);
        s.z = fmaf(v, w.z, s.z); s.w = fmaf(v, w.w, s.w);
    }
    __nv_bfloat16 hi[4];
    hi[0] = __float2bfloat16(s.x); hi[1] = __float2bfloat16(s.y);
    hi[2] = __float2bfloat16(s.z); hi[3] = __float2bfloat16(s.w);
    *(uint2*)&g_We_hi[e] = *(uint2*)hi;

    const float4 w = *(const float4*)&Wi[e];
    hi[0] = __float2bfloat16(w.x); hi[1] = __float2bfloat16(w.y);
    hi[2] = __float2bfloat16(w.z); hi[3] = __float2bfloat16(w.w);
    *(uint2*)&g_Wi_hi[e] = *(uint2*)hi;
}

// ---------------- kernel 3: x -> bf16 ----------------
__global__ void split_x_kernel(const float* __restrict__ x) {
    const int e = (blockIdx.x * blockDim.x + threadIdx.x) * 4;
    const float4 v4 = *(const float4*)&x[e];
    __nv_bfloat16 hi[4];
    hi[0] = __float2bfloat16(v4.x);
    hi[1] = __float2bfloat16(v4.y);
    hi[2] = __float2bfloat16(v4.z);
    hi[3] = __float2bfloat16(v4.w);
    *(uint2*)&g_x_hi[e] = *(uint2*)hi;
}

// ---------------- kernel 4: coherent reduction (pure BW) ----------------
__global__ void coh_reduce_kernel(const float* __restrict__ coh) {
    const int idx = blockIdx.x * blockDim.x + threadIdx.x;
    const int e = idx * 4;
    const int b = e >> 10;
    const int h = e & 1023;
    float4 acc = make_float4(0.f, 0.f, 0.f, 0.f);
#pragma unroll
    for (int j = 0; j < NP; j++) {
        const float4 c = *(const float4*)&coh[((size_t)b * NP + j) * HD + h];
        const float w = g_cw[j];
        acc.x = fmaf(w, c.x, acc.x);
        acc.y = fmaf(w, c.y, acc.y);
        acc.z = fmaf(w, c.z, acc.z);
        acc.w = fmaf(w, c.w, acc.w);
    }
    *(float4*)&g_cr[e] = acc;
}

// ---------------- kernel 5: combine split-K partials -> M bf16 ----------------
__global__ void fix_m_kernel() {
    const int e = (blockIdx.x * blockDim.x + threadIdx.x) * 4;
    const float4 p0 = *(const float4*)&g_P[e];
    const float4 p1 = *(const float4*)&g_P[HD * HD + e];
    __nv_bfloat16 hi[4];
    hi[0] = __float2bfloat16(p0.x + p1.x);
    hi[1] = __float2bfloat16(p0.y + p1.y);
    hi[2] = __float2bfloat16(p0.z + p1.z);
    hi[3] = __float2bfloat16(p0.w + p1.w);
    *(uint2*)&g_M_hi[e] = *(uint2*)hi;
}

// ---------------- cp.async helper ----------------
__device__ __forceinline__ void cp16(void* s, const void* g) {
    unsigned sa = (unsigned)__cvta_generic_to_shared(s);
    asm volatile("cp.async.cg.shared.global [%0], [%1], 16;\n" :: "r"(sa), "l"(g));
}
#define CP_COMMIT() asm volatile("cp.async.commit_group;\n")
#define CP_WAIT1()  asm volatile("cp.async.wait_group 1;\n")
#define CP_WAIT0()  asm volatile("cp.async.wait_group 0;\n")

// ---------------- GEMM1: single-pass bf16, tile 128x128, split-K=2 ----------------
// 256 thr = 8 warps (4m x 2n); warp tile 32x64 = 2x4 wmma tiles. f32 partial out.
__global__ void __launch_bounds__(256) gemm1_kernel() {
    constexpr int A_ONE = BM * APITCH * 2;        // 10240
    constexpr int B_ONE = BK1 * BPITCH * 2;       // 8704
    constexpr int OFF_B = A_ONE;
    constexpr int STAGE = A_ONE + B_ONE;          // 18944

    extern __shared__ __align__(16) unsigned char smem[];

    float* __restrict__ Cout = g_P + (size_t)blockIdx.z * HD * HD;
    const int kOff = blockIdx.z * (HD / 2);

    const int tid    = threadIdx.x;
    const int wid    = tid >> 5;
    const int warp_m = wid & 3;        // 32-row strip
    const int warp_n = wid >> 2;       // 64-col strip
    const int mBase  = blockIdx.y * BM;
    const int nBase  = blockIdx.x * BN;

    auto load_stage = [&](int s, int kt) {
        const int k0 = kOff + kt * BK1;
        unsigned char* st = smem + s * STAGE;
        // A: 128 rows x 32 cols = 512 x 16B chunks -> 2/thread
#pragma unroll
        for (int i = 0; i < 2; i++) {
            const int c   = tid + i * 256;
            const int row = c >> 2;
            const int ch  = c & 3;
            cp16(st + row * (APITCH * 2) + ch * 16,
                 g_Wi_hi + (size_t)(mBase + row) * HD + k0 + ch * 8);
        }
        // B: 32 rows x 128 cols = 512 x 16B chunks -> 2/thread
#pragma unroll
        for (int i = 0; i < 2; i++) {
            const int c   = tid + i * 256;
            const int row = c >> 4;
            const int ch  = c & 15;
            cp16(st + OFF_B + row * (BPITCH * 2) + ch * 16,
                 g_We_hi + (size_t)(k0 + row) * HD + nBase + ch * 8);
        }
        CP_COMMIT();
    };

    wmma::fragment<wmma::accumulator, 16, 16, 16, float> acc[2][4];
#pragma unroll
    for (int mi = 0; mi < 2; mi++)
#pragma unroll
        for (int ni = 0; ni < 4; ni++) wmma::fill_fragment(acc[mi][ni], 0.0f);

    load_stage(0, 0);
    load_stage(1, 1);

    for (int it = 0; it < NT1; ++it) {
        if (it + 1 < NT1) CP_WAIT1(); else CP_WAIT0();
        __syncthreads();
        if (it + 2 < NT1) load_stage((it + 2) % 3, it + 2);

        const unsigned char* st = smem + (it % 3) * STAGE;
        const __nv_bfloat16* pA = (const __nv_bfloat16*)(st);
        const __nv_bfloat16* pB = (const __nv_bfloat16*)(st + OFF_B);

#pragma unroll
        for (int kc = 0; kc < 2; kc++) {
            wmma::fragment<wmma::matrix_a, 16, 16, 16, __nv_bfloat16, wmma::row_major> fa[2];
            wmma::fragment<wmma::matrix_b, 16, 16, 16, __nv_bfloat16, wmma::row_major> fb[4];
#pragma unroll
            for (int mi = 0; mi < 2; mi++)
                wmma::load_matrix_sync(fa[mi], pA + (warp_m * 32 + mi * 16) * APITCH + kc * 16, APITCH);
#pragma unroll
            for (int ni = 0; ni < 4; ni++)
                wmma::load_matrix_sync(fb[ni], pB + (kc * 16) * BPITCH + warp_n * 64 + ni * 16, BPITCH);
#pragma unroll
            for (int mi = 0; mi < 2; mi++)
#pragma unroll
                for (int ni = 0; ni < 4; ni++)
                    wmma::mma_sync(acc[mi][ni], fa[mi], fb[ni], acc[mi][ni]);
        }
    }

#pragma unroll
    for (int mi = 0; mi < 2; mi++)
#pragma unroll
        for (int ni = 0; ni < 4; ni++) {
            float* cp = Cout + (size_t)(mBase + warp_m * 32 + mi * 16) * HD
                      + nBase + warp_n * 64 + ni * 16;
            wmma::store_matrix_sync(cp, acc[mi][ni], HD, wmma::mem_row_major);
        }
}

// ---------------- GEMM2: single-pass bf16, tile 128x128, BK=64 ----------------
// 256 thr = 8 warps (4m x 2n); warp tile 32x64 = 2x4 wmma. out = x@M + g_cr.
__global__ void __launch_bounds__(256) gemm2_kernel(float* __restrict__ Cf) {
    constexpr int A_ONE = BM * AP2 * 2;        // 18432
    constexpr int B_ONE = BK2 * BPITCH * 2;    // 17408
    constexpr int OFF_B = A_ONE;
    constexpr int STAGE = A_ONE + B_ONE;       // 35840

    extern __shared__ __align__(16) unsigned char smem[];

    const int tid    = threadIdx.x;
    const int wid    = tid >> 5;
    const int lane   = tid & 31;
    const int warp_m = wid & 3;
    const int warp_n = wid >> 2;
    const int mBase  = blockIdx.y * BM;
    const int nBase  = blockIdx.x * BN;

    auto load_stage = [&](int s, int kt) {
        const int k0 = kt * BK2;
        unsigned char* st = smem + s * STAGE;
        // A: 128 rows x 64 cols = 1024 x 16B -> 4/thread
#pragma unroll
        for (int i = 0; i < 4; i++) {
            const int c   = tid + i * 256;
            const int row = c >> 3;
            const int ch  = c & 7;
            cp16(st + row * (AP2 * 2) + ch * 16,
                 g_x_hi + (size_t)(mBase + row) * HD + k0 + ch * 8);
        }
        // B: 64 rows x 128 cols = 1024 x 16B -> 4/thread
#pragma unroll
        for (int i = 0; i < 4; i++) {
            const int c   = tid + i * 256;
            const int row = c >> 4;
            const int ch  = c & 15;
            cp16(st + OFF_B + row * (BPITCH * 2) + ch * 16,
                 g_M_hi + (size_t)(k0 + row) * HD + nBase + ch * 8);
        }
        CP_COMMIT();
    };

    wmma::fragment<wmma::accumulator, 16, 16, 16, float> acc[2][4];
#pragma unroll
    for (int mi = 0; mi < 2; mi++)
#pragma unroll
        for (int ni = 0; ni < 4; ni++) wmma::fill_fragment(acc[mi][ni], 0.0f);

    load_stage(0, 0);
    load_stage(1, 1);

    for (int it = 0; it < NT2; ++it) {
        if (it + 1 < NT2) CP_WAIT1(); else CP_WAIT0();
        __syncthreads();
        if (it + 2 < NT2) load_stage((it + 2) % 3, it + 2);

        const unsigned char* st = smem + (it % 3) * STAGE;
        const __nv_bfloat16* pA = (const __nv_bfloat16*)(st);
        const __nv_bfloat16* pB = (const __nv_bfloat16*)(st + OFF_B);

#pragma unroll
        for (int kc = 0; kc < 4; kc++) {
            wmma::fragment<wmma::matrix_a, 16, 16, 16, __nv_bfloat16, wmma::row_major> fa[2];
            wmma::fragment<wmma::matrix_b, 16, 16, 16, __nv_bfloat16, wmma::row_major> fb[4];
#pragma unroll
            for (int mi = 0; mi < 2; mi++)
                wmma::load_matrix_sync(fa[mi], pA + (warp_m * 32 + mi * 16) * AP2 + kc * 16, AP2);
#pragma unroll
            for (int ni = 0; ni < 4; ni++)
                wmma::load_matrix_sync(fb[ni], pB + (kc * 16) * BPITCH + warp_n * 64 + ni * 16, BPITCH);
#pragma unroll
            for (int mi = 0; mi < 2; mi++)
#pragma unroll
                for (int ni = 0; ni < 4; ni++)
                    wmma::mma_sync(acc[mi][ni], fa[mi], fb[ni], acc[mi][ni]);
        }
    }

    // epilogue: stage 16x64 per warp via smem, add g_cr, float4 store
    __syncthreads();
    float* buf = (float*)smem + wid * 1024;
#pragma unroll
    for (int mi = 0; mi < 2; mi++) {
#pragma unroll
        for (int ni = 0; ni < 4; ni++)
            wmma::store_matrix_sync(buf + ni * 16, acc[mi][ni], 64, wmma::mem_row_major);
        __syncwarp();
#pragma unroll
        for (int p = 0; p < 8; p++) {
            const int idx = p * 128 + lane * 4;
            const int r   = idx >> 6;
            const int c   = idx & 63;
            float4 v = *(float4*)&buf[r * 64 + c];
            const int b   = mBase + warp_m * 32 + mi * 16 + r;
            const int col = nBase + warp_n * 64 + c;
            const float4 cr = *(const float4*)&g_cr[(size_t)b * HD + col];
            v.x += cr.x; v.y += cr.y; v.z += cr.z; v.w += cr.w;
            *(float4*)&Cf[(size_t)b * HD + col] = v;
        }
        __syncwarp();
    }
}

#define SMB1 (3 * (BM * APITCH * 2 + BK1 * BPITCH * 2))   // 56832
#define SMB2 (3 * (BM * AP2 * 2 + BK2 * BPITCH * 2))      // 107520

// ---------------- launch ----------------
extern "C" void kernel_launch(void* const* d_in, const int* in_sizes, int n_in,
                              void* d_out, int out_size) {
    (void)in_sizes; (void)n_in; (void)out_size;
    const float* x   = (const float*)d_in[0];
    const float* Wi  = (const float*)d_in[1];
    const float* Wp  = (const float*)d_in[2];
    const float* J   = (const float*)d_in[3];
    const float* coh = (const float*)d_in[4];
    const float* t   = (const float*)d_in[5];
    float* out = (float*)d_out;

    cudaFuncSetAttribute(gemm1_kernel, cudaFuncAttributeMaxDynamicSharedMemorySize, SMB1);
    cudaFuncSetAttribute(gemm2_kernel, cudaFuncAttributeMaxDynamicSharedMemorySize, SMB2);

    prep_kernel<<<1, 32>>>(J, t);
    build_weff_kernel<<<(HD * HD / 4) / 256, 256>>>(Wp, Wi);
    split_x_kernel<<<(BD * HD / 4) / 256, 256>>>(x);
    coh_reduce_kernel<<<(BD * HD / 4) / 256, 256>>>(coh);

    {   // GEMM1 single-pass split-K=2: grid 8 x 8 x 2 = 128 CTAs
        dim3 g(HD / BN, HD / BM, 2);
        gemm1_kernel<<<g, 256, SMB1>>>();
    }
    fix_m_kernel<<<(HD * HD / 4) / 256, 256>>>();
    {   // GEMM2 single-pass: grid 8 x 16 = 128 CTAs
        dim3 g(HD / BN, BD / BM);
        gemm2_kernel<<<g, 256, SMB2>>>(out);
    }
}

// round 14
// speedup vs baseline: 1.6624x; 1.0196x over previous
#include <cuda_runtime.h>
#include <cuda_bf16.h>
#include <mma.h>
#include <cstdint>

using namespace nvcuda;

#define NP 8
#define HD 1024
#define BD 2048
#define BM 128
#define BN 128
#define APITCH 40        // gemm1 A pitch: 32+8 elems
#define BPITCH 136       // B pitch: 128+8 elems
#define AP2 72           // gemm2 A pitch: 64+8 elems
#define BK1 32
#define BK2 64
#define NT1 16           // 512/32 per split-K half
#define NT2 16           // 1024/64

// ---------------- device scratch ----------------
__device__ float g_v[NP];    // (1-alpha)*u[j]
__device__ float g_cw[NP];   // alpha*u[j]

__device__ __nv_bfloat16 g_Wi_hi[HD * HD];   // A1 (bf16)
__device__ __nv_bfloat16 g_We_hi[HD * HD];   // B1 (bf16)
__device__ __nv_bfloat16 g_M_hi[HD * HD];    // B2
__device__ __nv_bfloat16 g_x_hi[BD * HD];    // A2
__device__ float g_P[2 * HD * HD];           // gemm1 split-K partials
__device__ float g_cr[BD * HD];              // coherent reduction

// ---------------- kernel 1: scalars ----------------
__global__ void prep_kernel(const float* __restrict__ J, const float* __restrict__ t_ptr) {
    if (threadIdx.x != 0) return;
    const float t = t_ptr[0];
    float alpha = expf(-t / 51.0f);
    alpha = fminf(fmaxf(alpha, 0.0f), 1.0f);
    const float phase = 2.0f * 3.14159265358979323846f * 20.0f * t / 1000.0f;
    float colsum[NP];
#pragma unroll
    for (int j = 0; j < NP; j++) colsum[j] = 0.0f;
    for (int i = 0; i < NP; i++) {
        float row[NP];
        float mx = -1e30f;
#pragma unroll
        for (int j = 0; j < NP; j++) {
            float js = 0.5f * (J[i * NP + j] + J[j * NP + i]);
            row[j] = cosf(phase * js);
            mx = fmaxf(mx, row[j]);
        }
        float s = 0.0f;
#pragma unroll
        for (int j = 0; j < NP; j++) { row[j] = expf(row[j] - mx); s += row[j]; }
        float inv_s = 1.0f / s;
#pragma unroll
        for (int j = 0; j < NP; j++) colsum[j] += row[j] * inv_s;
    }
    const float scale = alpha / (float)(NP * NP);
#pragma unroll
    for (int j = 0; j < NP; j++) {
        float u = scale * colsum[j];
        g_v[j]  = (1.0f - alpha) * u;
        g_cw[j] = alpha * u;
    }
}

// ---------------- kernel 2: W_eff build + W_input -> bf16 ----------------
__global__ void build_weff_kernel(const float* __restrict__ Wp, const float* __restrict__ Wi) {
    const int e = (blockIdx.x * blockDim.x + threadIdx.x) * 4;
    float4 s = make_float4(0.f, 0.f, 0.f, 0.f);
#pragma unroll
    for (int j = 0; j < NP; j++) {
        const float4 w = *(const float4*)&Wp[(size_t)j * (HD * HD) + e];
        const float v = g_v[j];
        s.x = fmaf(v, w.x, s.x); s.y = fmaf(v, w.y, s.y);
        s.z = fmaf(v, w.z, s.z); s.w = fmaf(v, w.w, s.w);
    }
    __nv_bfloat16 hi[4];
    hi[0] = __float2bfloat16(s.x); hi[1] = __float2bfloat16(s.y);
    hi[2] = __float2bfloat16(s.z); hi[3] = __float2bfloat16(s.w);
    *(uint2*)&g_We_hi[e] = *(uint2*)hi;

    const float4 w = *(const float4*)&Wi[e];
    hi[0] = __float2bfloat16(w.x); hi[1] = __float2bfloat16(w.y);
    hi[2] = __float2bfloat16(w.z); hi[3] = __float2bfloat16(w.w);
    *(uint2*)&g_Wi_hi[e] = *(uint2*)hi;
}

// ---------------- kernel 3: fused x->bf16 + coherent reduction ----------------
__global__ void ew_kernel(const float* __restrict__ x, const float* __restrict__ coh) {
    const int idx = blockIdx.x * blockDim.x + threadIdx.x;
    const int e = idx * 4;
    const int b = e >> 10;
    const int h = e & 1023;

    const float4 v4 = *(const float4*)&x[e];
    __nv_bfloat16 hi[4];
    hi[0] = __float2bfloat16(v4.x);
    hi[1] = __float2bfloat16(v4.y);
    hi[2] = __float2bfloat16(v4.z);
    hi[3] = __float2bfloat16(v4.w);
    *(uint2*)&g_x_hi[e] = *(uint2*)hi;

    float4 acc = make_float4(0.f, 0.f, 0.f, 0.f);
#pragma unroll
    for (int j = 0; j < NP; j++) {
        const float4 c = *(const float4*)&coh[((size_t)b * NP + j) * HD + h];
        const float w = g_cw[j];
        acc.x = fmaf(w, c.x, acc.x);
        acc.y = fmaf(w, c.y, acc.y);
        acc.z = fmaf(w, c.z, acc.z);
        acc.w = fmaf(w, c.w, acc.w);
    }
    *(float4*)&g_cr[e] = acc;
}

// ---------------- kernel 4: combine split-K partials -> M bf16 ----------------
__global__ void fix_m_kernel() {
    const int e = (blockIdx.x * blockDim.x + threadIdx.x) * 4;
    const float4 p0 = *(const float4*)&g_P[e];
    const float4 p1 = *(const float4*)&g_P[HD * HD + e];
    __nv_bfloat16 hi[4];
    hi[0] = __float2bfloat16(p0.x + p1.x);
    hi[1] = __float2bfloat16(p0.y + p1.y);
    hi[2] = __float2bfloat16(p0.z + p1.z);
    hi[3] = __float2bfloat16(p0.w + p1.w);
    *(uint2*)&g_M_hi[e] = *(uint2*)hi;
}

// ---------------- cp.async helper ----------------
__device__ __forceinline__ void cp16(void* s, const void* g) {
    unsigned sa = (unsigned)__cvta_generic_to_shared(s);
    asm volatile("cp.async.cg.shared.global [%0], [%1], 16;\n" :: "r"(sa), "l"(g));
}
#define CP_COMMIT() asm volatile("cp.async.commit_group;\n")
#define CP_WAIT1()  asm volatile("cp.async.wait_group 1;\n")
#define CP_WAIT0()  asm volatile("cp.async.wait_group 0;\n")

// ---------------- GEMM1: single-pass bf16, tile 128x128, 4 warps (64x64/warp), split-K=2 ----
__global__ void __launch_bounds__(128) gemm1_kernel() {
    constexpr int A_ONE = BM * APITCH * 2;        // 10240
    constexpr int B_ONE = BK1 * BPITCH * 2;       // 8704
    constexpr int OFF_B = A_ONE;
    constexpr int STAGE = A_ONE + B_ONE;          // 18944

    extern __shared__ __align__(16) unsigned char smem[];

    float* __restrict__ Cout = g_P + (size_t)blockIdx.z * HD * HD;
    const int kOff = blockIdx.z * (HD / 2);

    const int tid    = threadIdx.x;
    const int wid    = tid >> 5;
    const int warp_m = wid & 1;        // 64-row strip
    const int warp_n = wid >> 1;       // 64-col strip
    const int mBase  = blockIdx.y * BM;
    const int nBase  = blockIdx.x * BN;

    auto load_stage = [&](int s, int kt) {
        const int k0 = kOff + kt * BK1;
        unsigned char* st = smem + s * STAGE;
        // A: 128 rows x 32 cols = 512 x 16B chunks -> 4/thread
#pragma unroll
        for (int i = 0; i < 4; i++) {
            const int c   = tid + i * 128;
            const int row = c >> 2;
            const int ch  = c & 3;
            cp16(st + row * (APITCH * 2) + ch * 16,
                 g_Wi_hi + (size_t)(mBase + row) * HD + k0 + ch * 8);
        }
        // B: 32 rows x 128 cols = 512 x 16B chunks -> 4/thread
#pragma unroll
        for (int i = 0; i < 4; i++) {
            const int c   = tid + i * 128;
            const int row = c >> 4;
            const int ch  = c & 15;
            cp16(st + OFF_B + row * (BPITCH * 2) + ch * 16,
                 g_We_hi + (size_t)(k0 + row) * HD + nBase + ch * 8);
        }
        CP_COMMIT();
    };

    wmma::fragment<wmma::accumulator, 16, 16, 16, float> acc[4][4];
#pragma unroll
    for (int mi = 0; mi < 4; mi++)
#pragma unroll
        for (int ni = 0; ni < 4; ni++) wmma::fill_fragment(acc[mi][ni], 0.0f);

    load_stage(0, 0);
    load_stage(1, 1);

    for (int it = 0; it < NT1; ++it) {
        if (it + 1 < NT1) CP_WAIT1(); else CP_WAIT0();
        __syncthreads();
        if (it + 2 < NT1) load_stage((it + 2) % 3, it + 2);

        const unsigned char* st = smem + (it % 3) * STAGE;
        const __nv_bfloat16* pA = (const __nv_bfloat16*)(st);
        const __nv_bfloat16* pB = (const __nv_bfloat16*)(st + OFF_B);

#pragma unroll
        for (int kc = 0; kc < 2; kc++) {
            wmma::fragment<wmma::matrix_a, 16, 16, 16, __nv_bfloat16, wmma::row_major> fa[4];
            wmma::fragment<wmma::matrix_b, 16, 16, 16, __nv_bfloat16, wmma::row_major> fb[4];
#pragma unroll
            for (int mi = 0; mi < 4; mi++)
                wmma::load_matrix_sync(fa[mi], pA + (warp_m * 64 + mi * 16) * APITCH + kc * 16, APITCH);
#pragma unroll
            for (int ni = 0; ni < 4; ni++)
                wmma::load_matrix_sync(fb[ni], pB + (kc * 16) * BPITCH + warp_n * 64 + ni * 16, BPITCH);
#pragma unroll
            for (int mi = 0; mi < 4; mi++)
#pragma unroll
                for (int ni = 0; ni < 4; ni++)
                    wmma::mma_sync(acc[mi][ni], fa[mi], fb[ni], acc[mi][ni]);
        }
    }

#pragma unroll
    for (int mi = 0; mi < 4; mi++)
#pragma unroll
        for (int ni = 0; ni < 4; ni++) {
            float* cp = Cout + (size_t)(mBase + warp_m * 64 + mi * 16) * HD
                      + nBase + warp_n * 64 + ni * 16;
            wmma::store_matrix_sync(cp, acc[mi][ni], HD, wmma::mem_row_major);
        }
}

// ---------------- GEMM2: single-pass bf16, tile 128x128, 4 warps (64x64/warp), BK=64 ----
__global__ void __launch_bounds__(128) gemm2_kernel(float* __restrict__ Cf) {
    constexpr int A_ONE = BM * AP2 * 2;        // 18432
    constexpr int B_ONE = BK2 * BPITCH * 2;    // 17408
    constexpr int OFF_B = A_ONE;
    constexpr int STAGE = A_ONE + B_ONE;       // 35840

    extern __shared__ __align__(16) unsigned char smem[];

    const int tid    = threadIdx.x;
    const int wid    = tid >> 5;
    const int lane   = tid & 31;
    const int warp_m = wid & 1;
    const int warp_n = wid >> 1;
    const int mBase  = blockIdx.y * BM;
    const int nBase  = blockIdx.x * BN;

    auto load_stage = [&](int s, int kt) {
        const int k0 = kt * BK2;
        unsigned char* st = smem + s * STAGE;
        // A: 128 rows x 64 cols = 1024 x 16B -> 8/thread
#pragma unroll
        for (int i = 0; i < 8; i++) {
            const int c   = tid + i * 128;
            const int row = c >> 3;
            const int ch  = c & 7;
            cp16(st + row * (AP2 * 2) + ch * 16,
                 g_x_hi + (size_t)(mBase + row) * HD + k0 + ch * 8);
        }
        // B: 64 rows x 128 cols = 1024 x 16B -> 8/thread
#pragma unroll
        for (int i = 0; i < 8; i++) {
            const int c   = tid + i * 128;
            const int row = c >> 4;
            const int ch  = c & 15;
            cp16(st + OFF_B + row * (BPITCH * 2) + ch * 16,
                 g_M_hi + (size_t)(k0 + row) * HD + nBase + ch * 8);
        }
        CP_COMMIT();
    };

    wmma::fragment<wmma::accumulator, 16, 16, 16, float> acc[4][4];
#pragma unroll
    for (int mi = 0; mi < 4; mi++)
#pragma unroll
        for (int ni = 0; ni < 4; ni++) wmma::fill_fragment(acc[mi][ni], 0.0f);

    load_stage(0, 0);
    load_stage(1, 1);

    for (int it = 0; it < NT2; ++it) {
        if (it + 1 < NT2) CP_WAIT1(); else CP_WAIT0();
        __syncthreads();
        if (it + 2 < NT2) load_stage((it + 2) % 3, it + 2);

        const unsigned char* st = smem + (it % 3) * STAGE;
        const __nv_bfloat16* pA = (const __nv_bfloat16*)(st);
        const __nv_bfloat16* pB = (const __nv_bfloat16*)(st + OFF_B);

#pragma unroll
        for (int kc = 0; kc < 4; kc++) {
            wmma::fragment<wmma::matrix_a, 16, 16, 16, __nv_bfloat16, wmma::row_major> fa[4];
            wmma::fragment<wmma::matrix_b, 16, 16, 16, __nv_bfloat16, wmma::row_major> fb[4];
#pragma unroll
            for (int mi = 0; mi < 4; mi++)
                wmma::load_matrix_sync(fa[mi], pA + (warp_m * 64 + mi * 16) * AP2 + kc * 16, AP2);
#pragma unroll
            for (int ni = 0; ni < 4; ni++)
                wmma::load_matrix_sync(fb[ni], pB + (kc * 16) * BPITCH + warp_n * 64 + ni * 16, BPITCH);
#pragma unroll
            for (int mi = 0; mi < 4; mi++)
#pragma unroll
                for (int ni = 0; ni < 4; ni++)
                    wmma::mma_sync(acc[mi][ni], fa[mi], fb[ni], acc[mi][ni]);
        }
    }

    // epilogue: stage 16x64 per warp via smem, add g_cr, float4 store
    __syncthreads();
    float* buf = (float*)smem + wid * 1024;
#pragma unroll
    for (int mi = 0; mi < 4; mi++) {
#pragma unroll
        for (int ni = 0; ni < 4; ni++)
            wmma::store_matrix_sync(buf + ni * 16, acc[mi][ni], 64, wmma::mem_row_major);
        __syncwarp();
#pragma unroll
        for (int p = 0; p < 8; p++) {
            const int idx = p * 128 + lane * 4;
            const int r   = idx >> 6;
            const int c   = idx & 63;
            float4 v = *(float4*)&buf[r * 64 + c];
            const int b   = mBase + warp_m * 64 + mi * 16 + r;
            const int col = nBase + warp_n * 64 + c;
            const float4 cr = *(const float4*)&g_cr[(size_t)b * HD + col];
            v.x += cr.x; v.y += cr.y; v.z += cr.z; v.w += cr.w;
            *(float4*)&Cf[(size_t)b * HD + col] = v;
        }
        __syncwarp();
    }
}

#define SMB1 (3 * (BM * APITCH * 2 + BK1 * BPITCH * 2))   // 56832
#define SMB2 (3 * (BM * AP2 * 2 + BK2 * BPITCH * 2))      // 107520

// ---------------- launch ----------------
extern "C" void kernel_launch(void* const* d_in, const int* in_sizes, int n_in,
                              void* d_out, int out_size) {
    (void)in_sizes; (void)n_in; (void)out_size;
    const float* x   = (const float*)d_in[0];
    const float* Wi  = (const float*)d_in[1];
    const float* Wp  = (const float*)d_in[2];
    const float* J   = (const float*)d_in[3];
    const float* coh = (const float*)d_in[4];
    const float* t   = (const float*)d_in[5];
    float* out = (float*)d_out;

    cudaFuncSetAttribute(gemm1_kernel, cudaFuncAttributeMaxDynamicSharedMemorySize, SMB1);
    cudaFuncSetAttribute(gemm2_kernel, cudaFuncAttributeMaxDynamicSharedMemorySize, SMB2);

    prep_kernel<<<1, 32>>>(J, t);
    build_weff_kernel<<<(HD * HD / 4) / 256, 256>>>(Wp, Wi);
    ew_kernel<<<(BD * HD / 4) / 256, 256>>>(x, coh);

    {   // GEMM1 split-K=2: grid 8 x 8 x 2 = 128 CTAs, 128 thr
        dim3 g(HD / BN, HD / BM, 2);
        gemm1_kernel<<<g, 128, SMB1>>>();
    }
    fix_m_kernel<<<(HD * HD / 4) / 256, 256>>>();
    {   // GEMM2: grid 8 x 16 = 128 CTAs, 128 thr
        dim3 g(HD / BN, BD / BM);
        gemm2_kernel<<<g, 128, SMB2>>>(out);
    }
}